// round 3
// baseline (speedup 1.0000x reference)
#include <cuda_runtime.h>
#include <math.h>

// Problem constants
#define N_IMG 4
#define C_DIM 256
#define H_DIM 50
#define W_DIM 50
#define HW (H_DIM * W_DIM)
#define PH 7
#define PW 7
#define NBINS (PH * PW)
#define N_ROI 1024
#define OUT_PER_ROI (C_DIM * NBINS)   // 12544 floats
#define SPATIAL_SCALE 0.0625f

// fl(1/7) in fp32 — XLA rewrites (x / 7) into (x * fl(1/7)); we must match it.
#define RCP_7 0.14285714924335479736328125f

// Scratch: x transposed to [N][H][W][C] (channels-last) = 10.24 MB
__device__ float g_xt[N_IMG * HW * C_DIM];

// ---------------------------------------------------------------------------
// Transpose NCHW -> NHWC via 32x32 smem tiles.
// ---------------------------------------------------------------------------
__global__ void __launch_bounds__(1024) transpose_kernel(const float* __restrict__ x) {
    __shared__ float tile[32][33];
    const int n = blockIdx.z;
    const int hw0 = blockIdx.x * 32;
    const int c0  = blockIdx.y * 32;

    {
        const int c  = c0 + threadIdx.y;
        const int hw = hw0 + threadIdx.x;
        if (hw < HW) {
            tile[threadIdx.y][threadIdx.x] = x[(n * C_DIM + c) * HW + hw];
        }
    }
    __syncthreads();
    {
        const int hw = hw0 + threadIdx.y;
        const int c  = c0 + threadIdx.x;
        if (hw < HW) {
            g_xt[(n * HW + hw) * C_DIM + c] = tile[threadIdx.x][threadIdx.y];
        }
    }
}

// ---------------------------------------------------------------------------
// RoI max pooling. One block per roi. 256 threads = 4 bin-groups x 64 lanes.
// Each lane owns 4 channels (float4). Results staged in smem as [c][bin]
// (== linear output layout for this roi), then streamed out coalesced.
//
// Bin boundaries emulate XLA numerics exactly:
//   bh = rh * fl(1/7)   (reciprocal-multiply, NOT true division)
//   edges = floor/ceil of single fp32 multiplies (__fmul_rn: no contraction)
// ---------------------------------------------------------------------------
__global__ void __launch_bounds__(256) roipool_kernel(const float* __restrict__ rois,
                                                      float* __restrict__ out) {
    extern __shared__ float s_out[];   // OUT_PER_ROI floats = 50176 B

    const int roi = blockIdx.x;
    const float* r = rois + roi * 5;

    const int b  = (int)r[0];
    const int xs = (int)rintf(__fmul_rn(r[1], SPATIAL_SCALE));
    const int ys = (int)rintf(__fmul_rn(r[2], SPATIAL_SCALE));
    const int xe = (int)rintf(__fmul_rn(r[3], SPATIAL_SCALE));
    const int ye = (int)rintf(__fmul_rn(r[4], SPATIAL_SCALE));

    const float rw = (float)max(xe - xs + 1, 1);
    const float rh = (float)max(ye - ys + 1, 1);
    const float bh = __fmul_rn(rh, RCP_7);   // match XLA: multiply by rounded reciprocal
    const float bw = __fmul_rn(rw, RCP_7);

    const int lane = threadIdx.x & 63;   // 64 lanes -> 256 channels via float4
    const int grp  = threadIdx.x >> 6;   // 4 concurrent bins
    const int c0   = lane * 4;

    const float* __restrict__ base = g_xt + (size_t)b * HW * C_DIM;

    #pragma unroll 1
    for (int it = 0; it < 13; ++it) {
        const int bin = it * 4 + grp;
        if (bin < NBINS) {
            const int ph = bin / PW;
            const int pw = bin % PW;

            int hs = (int)floorf(__fmul_rn((float)ph,        bh)) + ys;
            int he = (int)ceilf (__fmul_rn((float)ph + 1.0f, bh)) + ys;
            int ws = (int)floorf(__fmul_rn((float)pw,        bw)) + xs;
            int we = (int)ceilf (__fmul_rn((float)pw + 1.0f, bw)) + xs;
            hs = min(max(hs, 0), H_DIM);
            he = min(max(he, 0), H_DIM);
            ws = min(max(ws, 0), W_DIM);
            we = min(max(we, 0), W_DIM);

            float m0 = -INFINITY, m1 = -INFINITY, m2 = -INFINITY, m3 = -INFINITY;
            const bool empty = (hs >= he) || (ws >= we);

            for (int h = hs; h < he; ++h) {
                const float* rowp = base + ((size_t)h * W_DIM) * C_DIM + c0;
                for (int w = ws; w < we; ++w) {
                    const float4 v = *(const float4*)(rowp + (size_t)w * C_DIM);
                    m0 = fmaxf(m0, v.x);
                    m1 = fmaxf(m1, v.y);
                    m2 = fmaxf(m2, v.z);
                    m3 = fmaxf(m3, v.w);
                }
            }
            if (empty) { m0 = m1 = m2 = m3 = 0.0f; }

            s_out[(c0 + 0) * NBINS + bin] = m0;
            s_out[(c0 + 1) * NBINS + bin] = m1;
            s_out[(c0 + 2) * NBINS + bin] = m2;
            s_out[(c0 + 3) * NBINS + bin] = m3;
        }
    }
    __syncthreads();

    // Coalesced streaming store: smem [c][bin] layout == out[roi, c, ph, pw].
    float4* __restrict__ o4 = (float4*)(out + (size_t)roi * OUT_PER_ROI);
    const float4* __restrict__ s4 = (const float4*)s_out;
    for (int i = threadIdx.x; i < OUT_PER_ROI / 4; i += 256) {
        o4[i] = s4[i];
    }
}

extern "C" void kernel_launch(void* const* d_in, const int* in_sizes, int n_in,
                              void* d_out, int out_size) {
    const float* x    = (const float*)d_in[0];
    const float* rois = (const float*)d_in[1];
    float* out        = (float*)d_out;

    (void)in_sizes; (void)n_in; (void)out_size;

    const int smem_bytes = OUT_PER_ROI * sizeof(float);  // 50176 B > 48 KB default
    cudaFuncSetAttribute(roipool_kernel,
                         cudaFuncAttributeMaxDynamicSharedMemorySize, smem_bytes);

    dim3 tgrid((HW + 31) / 32, C_DIM / 32, N_IMG);
    dim3 tblk(32, 32);
    transpose_kernel<<<tgrid, tblk>>>(x);

    roipool_kernel<<<N_ROI, 256, smem_bytes>>>(rois, out);
}

// round 4
// speedup vs baseline: 1.1654x; 1.1654x over previous
#include <cuda_runtime.h>
#include <math.h>

// Problem constants
#define N_IMG 4
#define C_DIM 256
#define H_DIM 50
#define W_DIM 50
#define HW (H_DIM * W_DIM)
#define PH 7
#define PW 7
#define NBINS (PH * PW)
#define N_ROI 1024
#define OUT_PER_ROI (C_DIM * NBINS)   // 12544 floats
#define HALF_C 128
#define HALF_OUT (HALF_C * NBINS)     // 6272 floats = 25088 B
#define SPATIAL_SCALE 0.0625f

// fl(1/7) in fp32 — XLA rewrites (x / 7) into (x * fl(1/7)); we must match it.
#define RCP_7 0.14285714924335479736328125f

// Scratch: x transposed to [N][H][W][C] (channels-last) = 10.24 MB
__device__ float g_xt[N_IMG * HW * C_DIM];

// ---------------------------------------------------------------------------
// Transpose NCHW -> NHWC via 32x32 smem tiles.
// ---------------------------------------------------------------------------
__global__ void __launch_bounds__(1024) transpose_kernel(const float* __restrict__ x) {
    __shared__ float tile[32][33];
    const int n = blockIdx.z;
    const int hw0 = blockIdx.x * 32;
    const int c0  = blockIdx.y * 32;

    {
        const int c  = c0 + threadIdx.y;
        const int hw = hw0 + threadIdx.x;
        if (hw < HW) {
            tile[threadIdx.y][threadIdx.x] = x[(n * C_DIM + c) * HW + hw];
        }
    }
    __syncthreads();
    {
        const int hw = hw0 + threadIdx.y;
        const int c  = c0 + threadIdx.x;
        if (hw < HW) {
            g_xt[(n * HW + hw) * C_DIM + c] = tile[threadIdx.x][threadIdx.y];
        }
    }
}

// ---------------------------------------------------------------------------
// RoI max pooling. One block per roi, 256 threads = 8 bin-groups x 32 lanes.
// Channels processed in two 128-channel halves so the smem staging buffer is
// 25 KB -> 8 CTAs/SM (100% occupancy), whole 1024-block grid in ONE wave.
// Each lane owns 4 channels (float4); w-loop unrolled x2 for MLP.
//
// Bin boundaries emulate XLA numerics exactly:
//   bh = rh * fl(1/7)   (reciprocal-multiply, NOT true division)
//   edges = floor/ceil of single fp32 multiplies (__fmul_rn: no contraction)
// ---------------------------------------------------------------------------
__global__ void __launch_bounds__(256) roipool_kernel(const float* __restrict__ rois,
                                                      float* __restrict__ out) {
    __shared__ float s_out[HALF_OUT];   // 25088 B

    const int roi = blockIdx.x;
    const float* r = rois + roi * 5;

    const int b  = (int)r[0];
    const int xs = (int)rintf(__fmul_rn(r[1], SPATIAL_SCALE));
    const int ys = (int)rintf(__fmul_rn(r[2], SPATIAL_SCALE));
    const int xe = (int)rintf(__fmul_rn(r[3], SPATIAL_SCALE));
    const int ye = (int)rintf(__fmul_rn(r[4], SPATIAL_SCALE));

    const float rw = (float)max(xe - xs + 1, 1);
    const float rh = (float)max(ye - ys + 1, 1);
    const float bh = __fmul_rn(rh, RCP_7);   // match XLA numerics
    const float bw = __fmul_rn(rw, RCP_7);

    const int lane = threadIdx.x & 31;   // 32 lanes -> 128 channels via float4
    const int grp  = threadIdx.x >> 5;   // 8 concurrent bins

    const float* __restrict__ imgbase = g_xt + (size_t)b * HW * C_DIM;

    #pragma unroll 1
    for (int half = 0; half < 2; ++half) {
        const int cl = lane * 4;                         // local channel in half
        const float* __restrict__ base = imgbase + half * HALF_C + cl;

        #pragma unroll 1
        for (int it = 0; it < 7; ++it) {
            const int bin = it * 8 + grp;
            if (bin < NBINS) {
                const int ph = bin / PW;
                const int pw = bin % PW;

                int hs = (int)floorf(__fmul_rn((float)ph,        bh)) + ys;
                int he = (int)ceilf (__fmul_rn((float)ph + 1.0f, bh)) + ys;
                int ws = (int)floorf(__fmul_rn((float)pw,        bw)) + xs;
                int we = (int)ceilf (__fmul_rn((float)pw + 1.0f, bw)) + xs;
                hs = min(max(hs, 0), H_DIM);
                he = min(max(he, 0), H_DIM);
                ws = min(max(ws, 0), W_DIM);
                we = min(max(we, 0), W_DIM);

                float m0 = -INFINITY, m1 = -INFINITY, m2 = -INFINITY, m3 = -INFINITY;
                const bool empty = (hs >= he) || (ws >= we);

                for (int h = hs; h < he; ++h) {
                    const float* rowp = base + (size_t)(h * W_DIM) * C_DIM;
                    int w = ws;
                    // unroll x2: two independent loads in flight
                    for (; w + 1 < we; w += 2) {
                        const float4 v0 = *(const float4*)(rowp + (size_t)w * C_DIM);
                        const float4 v1 = *(const float4*)(rowp + (size_t)(w + 1) * C_DIM);
                        m0 = fmaxf(fmaxf(m0, v0.x), v1.x);
                        m1 = fmaxf(fmaxf(m1, v0.y), v1.y);
                        m2 = fmaxf(fmaxf(m2, v0.z), v1.z);
                        m3 = fmaxf(fmaxf(m3, v0.w), v1.w);
                    }
                    if (w < we) {
                        const float4 v = *(const float4*)(rowp + (size_t)w * C_DIM);
                        m0 = fmaxf(m0, v.x);
                        m1 = fmaxf(m1, v.y);
                        m2 = fmaxf(m2, v.z);
                        m3 = fmaxf(m3, v.w);
                    }
                }
                if (empty) { m0 = m1 = m2 = m3 = 0.0f; }

                s_out[(cl + 0) * NBINS + bin] = m0;
                s_out[(cl + 1) * NBINS + bin] = m1;
                s_out[(cl + 2) * NBINS + bin] = m2;
                s_out[(cl + 3) * NBINS + bin] = m3;
            }
        }
        __syncthreads();

        // Coalesced streaming store of this half: smem [c_local][bin] layout
        // == out[roi, half*128 + c_local, ph, pw] (contiguous 25088 B).
        float4* __restrict__ o4 =
            (float4*)(out + (size_t)roi * OUT_PER_ROI + half * HALF_OUT);
        const float4* __restrict__ s4 = (const float4*)s_out;
        #pragma unroll 1
        for (int i = threadIdx.x; i < HALF_OUT / 4; i += 256) {
            o4[i] = s4[i];
        }
        __syncthreads();
    }
}

extern "C" void kernel_launch(void* const* d_in, const int* in_sizes, int n_in,
                              void* d_out, int out_size) {
    const float* x    = (const float*)d_in[0];
    const float* rois = (const float*)d_in[1];
    float* out        = (float*)d_out;

    (void)in_sizes; (void)n_in; (void)out_size;

    dim3 tgrid((HW + 31) / 32, C_DIM / 32, N_IMG);
    dim3 tblk(32, 32);
    transpose_kernel<<<tgrid, tblk>>>(x);

    roipool_kernel<<<N_ROI, 256>>>(rois, out);
}

// round 5
// speedup vs baseline: 1.3054x; 1.1201x over previous
#include <cuda_runtime.h>
#include <math.h>

// Problem constants
#define N_IMG 4
#define C_DIM 256
#define H_DIM 50
#define W_DIM 50
#define HW (H_DIM * W_DIM)
#define PH 7
#define PW 7
#define NBINS (PH * PW)
#define N_ROI 1024
#define OUT_PER_ROI (C_DIM * NBINS)   // 12544 floats
#define SPATIAL_SCALE 0.0625f

// fl(1/7) in fp32 — XLA rewrites (x / 7) into (x * fl(1/7)); we must match it.
#define RCP_7 0.14285714924335479736328125f

// Scratch: x transposed to [N][H][W][C] (channels-last) = 10.24 MB
__device__ float g_xt[N_IMG * HW * C_DIM];

// ---------------------------------------------------------------------------
// Transpose NCHW -> NHWC via 32x32 smem tiles.
// ---------------------------------------------------------------------------
__global__ void __launch_bounds__(1024) transpose_kernel(const float* __restrict__ x) {
    __shared__ float tile[32][33];
    const int n = blockIdx.z;
    const int hw0 = blockIdx.x * 32;
    const int c0  = blockIdx.y * 32;

    {
        const int c  = c0 + threadIdx.y;
        const int hw = hw0 + threadIdx.x;
        if (hw < HW) {
            tile[threadIdx.y][threadIdx.x] = x[(n * C_DIM + c) * HW + hw];
        }
    }
    __syncthreads();
    {
        const int hw = hw0 + threadIdx.y;
        const int c  = c0 + threadIdx.x;
        if (hw < HW) {
            g_xt[(n * HW + hw) * C_DIM + c] = tile[threadIdx.x][threadIdx.y];
        }
    }
}

// ---------------------------------------------------------------------------
// RoI max pooling, fine-grained: one block per (roi, ph-row).
// Grid = 1024 x 7.  Block = 256 threads = 4 pw-groups x 64 lanes.
// Each lane carries 4 channels (float4) -> 64 lanes = all 256 channels.
// Each pw-group handles pw = grp and pw = grp+4 (7 bins total per block).
// Results staged in smem [c][pw], then streamed to out[roi, c, ph, pw].
//
// __launch_bounds__(256, 6): cap regs at 42 so 6 CTAs/SM (48 warps, 75% occ);
// round 4 showed regs=52 silently capped residency at 4 CTAs/SM.
//
// Bin boundaries emulate XLA numerics exactly:
//   bh = rh * fl(1/7)   (reciprocal-multiply, NOT true division)
//   edges = floor/ceil of single fp32 multiplies (__fmul_rn: no contraction)
// ---------------------------------------------------------------------------
__global__ void __launch_bounds__(256, 6) roipool_kernel(const float* __restrict__ rois,
                                                         float* __restrict__ out) {
    __shared__ float s_out[C_DIM * PW];   // [c][pw]  = 1792 floats = 7168 B

    const int roi = blockIdx.x;
    const int ph  = blockIdx.y;
    const float* r = rois + roi * 5;

    const int b  = (int)r[0];
    const int xs = (int)rintf(__fmul_rn(r[1], SPATIAL_SCALE));
    const int ys = (int)rintf(__fmul_rn(r[2], SPATIAL_SCALE));
    const int xe = (int)rintf(__fmul_rn(r[3], SPATIAL_SCALE));
    const int ye = (int)rintf(__fmul_rn(r[4], SPATIAL_SCALE));

    const float rw = (float)max(xe - xs + 1, 1);
    const float rh = (float)max(ye - ys + 1, 1);
    const float bh = __fmul_rn(rh, RCP_7);   // match XLA numerics
    const float bw = __fmul_rn(rw, RCP_7);

    int hs = (int)floorf(__fmul_rn((float)ph,        bh)) + ys;
    int he = (int)ceilf (__fmul_rn((float)ph + 1.0f, bh)) + ys;
    hs = min(max(hs, 0), H_DIM);
    he = min(max(he, 0), H_DIM);

    const int lane = threadIdx.x & 63;   // 64 lanes -> 256 channels via float4
    const int grp  = threadIdx.x >> 6;   // 4 pw-groups
    const int c0   = lane * 4;

    const float* __restrict__ base = g_xt + (size_t)b * HW * C_DIM + c0;

    #pragma unroll 1
    for (int it = 0; it < 2; ++it) {
        const int pw = it * 4 + grp;
        if (pw < PW) {
            int ws = (int)floorf(__fmul_rn((float)pw,        bw)) + xs;
            int we = (int)ceilf (__fmul_rn((float)pw + 1.0f, bw)) + xs;
            ws = min(max(ws, 0), W_DIM);
            we = min(max(we, 0), W_DIM);

            float m0 = -INFINITY, m1 = -INFINITY, m2 = -INFINITY, m3 = -INFINITY;
            const bool empty = (hs >= he) || (ws >= we);

            #pragma unroll 1
            for (int h = hs; h < he; ++h) {
                const float* rowp = base + (size_t)(h * W_DIM) * C_DIM;
                int w = ws;
                for (; w + 1 < we; w += 2) {   // 2 independent loads in flight
                    const float4 v0 = *(const float4*)(rowp + (size_t)w * C_DIM);
                    const float4 v1 = *(const float4*)(rowp + (size_t)(w + 1) * C_DIM);
                    m0 = fmaxf(fmaxf(m0, v0.x), v1.x);
                    m1 = fmaxf(fmaxf(m1, v0.y), v1.y);
                    m2 = fmaxf(fmaxf(m2, v0.z), v1.z);
                    m3 = fmaxf(fmaxf(m3, v0.w), v1.w);
                }
                if (w < we) {
                    const float4 v = *(const float4*)(rowp + (size_t)w * C_DIM);
                    m0 = fmaxf(m0, v.x);
                    m1 = fmaxf(m1, v.y);
                    m2 = fmaxf(m2, v.z);
                    m3 = fmaxf(m3, v.w);
                }
            }
            if (empty) { m0 = m1 = m2 = m3 = 0.0f; }

            s_out[(c0 + 0) * PW + pw] = m0;
            s_out[(c0 + 1) * PW + pw] = m1;
            s_out[(c0 + 2) * PW + pw] = m2;
            s_out[(c0 + 3) * PW + pw] = m3;
        }
    }
    __syncthreads();

    // Store: out[roi, c, ph, pw] = s_out[c*7 + pw]; consecutive tid covers
    // consecutive (c,pw) -> near-coalesced 7-float runs per channel.
    float* __restrict__ obase = out + (size_t)roi * OUT_PER_ROI + ph * PW;
    #pragma unroll 1
    for (int i = threadIdx.x; i < C_DIM * PW; i += 256) {
        const int c  = i / PW;
        const int pw = i - c * PW;
        obase[c * NBINS + pw] = s_out[i];
    }
}

extern "C" void kernel_launch(void* const* d_in, const int* in_sizes, int n_in,
                              void* d_out, int out_size) {
    const float* x    = (const float*)d_in[0];
    const float* rois = (const float*)d_in[1];
    float* out        = (float*)d_out;

    (void)in_sizes; (void)n_in; (void)out_size;

    dim3 tgrid((HW + 31) / 32, C_DIM / 32, N_IMG);
    dim3 tblk(32, 32);
    transpose_kernel<<<tgrid, tblk>>>(x);

    dim3 pgrid(N_ROI, PH);
    roipool_kernel<<<pgrid, 256>>>(rois, out);
}